// round 16
// baseline (speedup 1.0000x reference)
#include <cuda_runtime.h>

#define BB 32
#define NN 4096
#define DD 256
#define HH 8
#define TT 28
#define ROWS (BB * NN)
#define BLK 128
#define T64 64                // rows per fused tile
#define NT (ROWS / T64)       // 2048 tiles
#define GRIDX (148 * 3)       // persistent: 3 CTAs per SM

typedef unsigned long long u64;

// ---------- packed f32x2 ops on opaque u64 register pairs ----------
__device__ __forceinline__ u64 ffma2(u64 a, u64 b, u64 c) {
    u64 d; asm("fma.rn.f32x2 %0, %1, %2, %3;" : "=l"(d) : "l"(a), "l"(b), "l"(c)); return d;
}
__device__ __forceinline__ u64 fadd2(u64 a, u64 b) {
    u64 d; asm("add.rn.f32x2 %0, %1, %2;" : "=l"(d) : "l"(a), "l"(b)); return d;
}
__device__ __forceinline__ u64 pk(float lo, float hi) {
    u64 r; asm("mov.b64 %0, {%1,%2};" : "=l"(r) : "f"(lo), "f"(hi)); return r;
}
__device__ __forceinline__ float2 upk(u64 v) {
    float2 f; asm("mov.b64 {%0,%1}, %2;" : "=f"(f.x), "=f"(f.y) : "l"(v)); return f;
}
__device__ __forceinline__ u64 dup2(float v) { return pk(v, v); }

__device__ __forceinline__ float tanhapx(float x) {
    float y; asm("tanh.approx.f32 %0, %1;" : "=f"(y) : "f"(x)); return y;
}

__device__ __forceinline__ void cp16(void* smem_dst, const void* gsrc) {
    unsigned sa = (unsigned)__cvta_generic_to_shared(smem_dst);
    asm volatile("cp.async.cg.shared.global [%0], [%1], 16;" :: "r"(sa), "l"(gsrc) : "memory");
}
__device__ __forceinline__ void cp_commit() {
    asm volatile("cp.async.commit_group;" ::: "memory");
}
__device__ __forceinline__ void cp_wait0() {
    asm volatile("cp.async.wait_group 0;" ::: "memory");
}
__device__ __forceinline__ void cp_wait1() {
    asm volatile("cp.async.wait_group 1;" ::: "memory");
}

// volatile v2.u64 shared load — NOT hoistable/CSE-able by ptxas (keeps GRU
// weights out of the register file during the proj phase)
__device__ __forceinline__ void lds2v(u64& a, u64& b, unsigned addr) {
    asm volatile("ld.volatile.shared.v2.u64 {%0, %1}, [%2];"
                 : "=l"(a), "=l"(b) : "r"(addr));
}

#define NEG1U 0xBF800000BF800000ULL  // (-1.0f, -1.0f)

// input pre-scaled by 0.5: sigmoid(2v) = 0.5*tanh(v) + 0.5
__device__ __forceinline__ u64 sigmoid2h(u64 v) {
    float2 f = upk(v);
    return pk(fmaf(0.5f, tanhapx(f.x), 0.5f), fmaf(0.5f, tanhapx(f.y), 0.5f));
}
__device__ __forceinline__ u64 tanh2t(u64 v) {
    float2 f = upk(v);
    return pk(tanhapx(f.x), tanhapx(f.y));
}

struct Smem {
    float4     xs[2][32][32];     // cp.async double buffer (32KB)
    ulonglong2 wq[64 * 17];       // proj weights, packed+padded (17KB)
    u64        res[T64][8];       // proj->GRU handoff: [row][0..3 h-pairs | 4..7 g1-pairs]
    u64        gf[T64][TT];       // (gate, (1-gate)*decay) (14KB)
    u64        gwq[4][28];        // GRU W: [sub][whr0..7|whz0..7|whn0..7|wo0..3]
    u64        gbias[4][8];       // [sub][wihr,wihz,wihn,bsr,bsz,bain,bahn,pad]
    u64        gpb[4][2];         // [sub][bpq, bg1q]
};

__global__ void __launch_bounds__(BLK)
fused_kernel(const float* __restrict__ x, const float* __restrict__ last_step,
             const float* __restrict__ W_ih, const float* __restrict__ W_hh,
             const float* __restrict__ b_ih, const float* __restrict__ b_hh,
             const float* __restrict__ Wp, const float* __restrict__ bp,
             const float* __restrict__ Wo, const float* __restrict__ bo,
             const float* __restrict__ Wg1, const float* __restrict__ bg1,
             const float* __restrict__ Wg2, const float* __restrict__ bg2,
             const float* __restrict__ log_decay, float* __restrict__ out) {
    extern __shared__ char smraw[];
    Smem& s = *reinterpret_cast<Smem*>(smraw);
    const int tid = threadIdx.x;
    const unsigned FULL = 0xFFFFFFFFu;

    // proj-phase roles
    const int pg  = tid >> 6;          // 0 = Wp, 1 = Wg1
    const int rgp = (tid >> 4) & 3;    // row group (8 rows)
    const int ds  = tid & 15;          // d-slice
    // GRU-phase roles
    const int sub = tid & 3;
    const int rl  = tid >> 2;          // 0..31

    // ---- pack proj weights (once per block) ----
    for (int idx = tid; idx < 64 * 16; idx += BLK) {
        int chunk = idx >> 4, r = idx & 15;
        int e = r >> 2, pgw = (r >> 1) & 1, i = r & 1;
        int d = chunk * 4 + e;
        const float* W = pgw ? Wg1 : Wp;
        s.wq[chunk * 17 + e * 4 + pgw * 2 + i] = make_ulonglong2(
            pk(W[(4 * i + 0) * DD + d], W[(4 * i + 1) * DD + d]),
            pk(W[(4 * i + 2) * DD + d], W[(4 * i + 3) * DD + d]));
    }

    // ---- pack GRU weights into smem (once per block; 4 threads) ----
    if (tid < 4) {
        int sb = tid, L0 = 2 * sb, L1 = L0 + 1;
        for (int p2 = 0; p2 < 4; p2++) {
            int j0 = 2 * (sb ^ p2);
            for (int b2 = 0; b2 < 2; b2++) {
                int j = j0 + b2, idx = 2 * p2 + b2;
                s.gwq[sb][idx]      = pk(0.5f * W_hh[L0 * HH + j],       0.5f * W_hh[L1 * HH + j]);
                s.gwq[sb][8 + idx]  = pk(0.5f * W_hh[(8 + L0) * HH + j], 0.5f * W_hh[(8 + L1) * HH + j]);
                s.gwq[sb][16 + idx] = pk(W_hh[(16 + L0) * HH + j],       W_hh[(16 + L1) * HH + j]);
            }
            s.gwq[sb][24 + p2] = pk(Wo[j0], Wo[j0 + 1]);
        }
        s.gbias[sb][0] = pk(0.5f * W_ih[L0], 0.5f * W_ih[L1]);
        s.gbias[sb][1] = pk(0.5f * W_ih[8 + L0], 0.5f * W_ih[8 + L1]);
        s.gbias[sb][2] = pk(W_ih[16 + L0], W_ih[16 + L1]);
        s.gbias[sb][3] = pk(0.5f * (b_ih[L0] + b_hh[L0]), 0.5f * (b_ih[L1] + b_hh[L1]));
        s.gbias[sb][4] = pk(0.5f * (b_ih[8 + L0] + b_hh[8 + L0]),
                            0.5f * (b_ih[8 + L1] + b_hh[8 + L1]));
        s.gbias[sb][5] = pk(b_ih[16 + L0], b_ih[16 + L1]);
        s.gbias[sb][6] = pk(b_hh[16 + L0], b_hh[16 + L1]);
        s.gbias[sb][7] = 0ULL;
        s.gpb[sb][0] = pk(bp[L0], bp[L1]);
        s.gpb[sb][1] = pk(bg1[L0], bg1[L1]);
    }

    const float bo_r = bo[0];
    const float edc  = __expf(log_decay[0]);

    auto issue_unit = [&](int row32, int cst, int buf) {
#pragma unroll
        for (int kk = 0; kk < 8; kk++) {
            int f = kk * BLK + tid;
            int row = f >> 5, q = f & 31;
            cp16(&s.xs[buf][row][q],
                 x + (size_t)(row32 + row) * DD + cst * 128 + q * 4);
        }
        cp_commit();
    };
    const int stride = gridDim.x;
    const int T0 = blockIdx.x;
    auto issue_k = [&](int k) {
        int T = T0 + (k >> 2) * stride;
        if (T >= NT) return;
        issue_unit(T * T64 + ((k >> 1) & 1) * 32, k & 1, k & 1);
    };

    // depth-2 pipeline prologue
    issue_k(0);
    issue_k(1);

    u64 acc[32];
    int k = 0;
#pragma unroll 1
    for (int T = T0; T < NT; T += stride) {
        // ================= proj phase: 4 units of 16KB =================
#pragma unroll 1
        for (int u = 0; u < 4; u++, k++) {
            if (T0 + ((k + 1) >> 2) * stride < NT) cp_wait1(); else cp_wait0();
            __syncthreads();
            int c = u & 1, g = u >> 1, buf = k & 1;
            if (c == 0) {
#pragma unroll
                for (int i = 0; i < 32; i++) acc[i] = 0ULL;
            }
#pragma unroll 1
            for (int m2 = 0; m2 < 2; m2++) {
                int chunkL = ds + 16 * m2;
                int chunkG = c * 32 + chunkL;
                ulonglong2 w[8];
#pragma unroll
                for (int e = 0; e < 4; e++) {
                    w[2 * e]     = s.wq[chunkG * 17 + e * 4 + pg * 2 + 0];
                    w[2 * e + 1] = s.wq[chunkG * 17 + e * 4 + pg * 2 + 1];
                }
#pragma unroll
                for (int r = 0; r < 8; r++) {
                    float4 xv = s.xs[buf][rgp * 8 + r][chunkL];
#pragma unroll
                    for (int e = 0; e < 4; e++) {
                        float xe = (e == 0) ? xv.x : (e == 1) ? xv.y : (e == 2) ? xv.z : xv.w;
                        u64 xd = dup2(xe);
                        acc[r * 4 + 0] = ffma2(w[2 * e].x,     xd, acc[r * 4 + 0]);
                        acc[r * 4 + 1] = ffma2(w[2 * e].y,     xd, acc[r * 4 + 1]);
                        acc[r * 4 + 2] = ffma2(w[2 * e + 1].x, xd, acc[r * 4 + 2]);
                        acc[r * 4 + 3] = ffma2(w[2 * e + 1].y, xd, acc[r * 4 + 3]);
                    }
                }
            }
            if (c == 1) {
#define REDROUND(cnt, bit) { int db = ds & (bit); \
    _Pragma("unroll") \
    for (int i = 0; i < (cnt) / 2; i++) { \
        u64 snd = db ? acc[i] : acc[i + (cnt) / 2]; \
        u64 rcv = __shfl_xor_sync(FULL, snd, (bit)); \
        u64 kp  = db ? acc[i + (cnt) / 2] : acc[i]; \
        acc[i] = fadd2(kp, rcv); \
    } }
                REDROUND(32, 1)
                REDROUND(16, 2)
                REDROUND(8, 4)
                REDROUND(4, 8)
#undef REDROUND
                int r_own = 4 * (ds & 1) + 2 * ((ds >> 1) & 1) + ((ds >> 2) & 1);
                int b = (ds >> 3) & 1;
                *(ulonglong2*)&s.res[g * 32 + rgp * 8 + r_own][pg * 4 + 2 * b] =
                    make_ulonglong2(acc[0], acc[1]);
            }
            __syncthreads();      // xs[buf] free + res visible
            issue_k(k + 2);       // prefetch two ahead (lands under GRU below)
        }

        // ================= GRU phase: rows T*64 .. T*64+63 =================
        {
            const int rowA = T * T64 + rl, rowB = rowA + 32;

            // re-load GRU weights via volatile LDS (not live during proj phase)
            u64 whr[8], whz[8], whn[8], wo4[4];
            unsigned gwb = (unsigned)__cvta_generic_to_shared(&s.gwq[sub][0]);
            lds2v(whr[0], whr[1], gwb + 0);    lds2v(whr[2], whr[3], gwb + 16);
            lds2v(whr[4], whr[5], gwb + 32);   lds2v(whr[6], whr[7], gwb + 48);
            lds2v(whz[0], whz[1], gwb + 64);   lds2v(whz[2], whz[3], gwb + 80);
            lds2v(whz[4], whz[5], gwb + 96);   lds2v(whz[6], whz[7], gwb + 112);
            lds2v(whn[0], whn[1], gwb + 128);  lds2v(whn[2], whn[3], gwb + 144);
            lds2v(whn[4], whn[5], gwb + 160);  lds2v(whn[6], whn[7], gwb + 176);
            lds2v(wo4[0], wo4[1], gwb + 192);  lds2v(wo4[2], wo4[3], gwb + 208);
            u64 wihr, wihz, wihn, bsr, bsz, bain, bahn, padv;
            unsigned gbb = (unsigned)__cvta_generic_to_shared(&s.gbias[sub][0]);
            lds2v(wihr, wihz, gbb + 0);  lds2v(wihn, bsr, gbb + 16);
            lds2v(bsz, bain, gbb + 32);  lds2v(bahn, padv, gbb + 48);
            (void)padv;
            u64 bpq, bg1q;
            unsigned gpbb = (unsigned)__cvta_generic_to_shared(&s.gpb[sub][0]);
            lds2v(bpq, bg1q, gpbb + 0);

            u64 hqA = fadd2(s.res[rl][sub], bpq);
            u64 hqB = fadd2(s.res[rl + 32][sub], bpq);
            u64 g1qA, g1qB;
            {
                float2 f = upk(fadd2(s.res[rl][4 + sub], bg1q));
                g1qA = pk(fmaxf(f.x, 0.0f), fmaxf(f.y, 0.0f));
                float2 g = upk(fadd2(s.res[rl + 32][4 + sub], bg1q));
                g1qB = pk(fmaxf(g.x, 0.0f), fmaxf(g.y, 0.0f));
            }
            const float lastA = last_step[rowA];
            const float lastB = last_step[rowB];

            // precompute (gate, (1-gate)*decay) per t for both rows
            {
                int j0 = 2 * (sub ^ 0), j1 = 2 * (sub ^ 1);
                int j2 = 2 * (sub ^ 2), j3 = 2 * (sub ^ 3);
#pragma unroll
                for (int which = 0; which < 2; which++) {
                    u64 gq = which ? g1qB : g1qA;
                    float lastv = which ? lastB : lastA;
                    int rloc = rl + 32 * which;
                    u64 gA = __shfl_xor_sync(FULL, gq, 1);
                    u64 gB = __shfl_xor_sync(FULL, gq, 2);
                    u64 gC = __shfl_xor_sync(FULL, gq, 3);
                    float2 g0 = upk(gq), g1v = upk(gA), g2v = upk(gB), g3v = upk(gC);
#pragma unroll
                    for (int kk = 0; kk < 7; kk++) {
                        int t = 4 * kk + sub;
                        const float* wr = Wg2 + t * HH;
                        float lg = bg2[t];
                        lg = fmaf(g0.x, wr[j0], lg);   lg = fmaf(g0.y, wr[j0 + 1], lg);
                        lg = fmaf(g1v.x, wr[j1], lg);  lg = fmaf(g1v.y, wr[j1 + 1], lg);
                        lg = fmaf(g2v.x, wr[j2], lg);  lg = fmaf(g2v.y, wr[j2 + 1], lg);
                        lg = fmaf(g3v.x, wr[j3], lg);  lg = fmaf(g3v.y, wr[j3 + 1], lg);
                        float gate = fmaf(0.5f, tanhapx(0.5f * lg), 0.5f);
                        float gd = lastv * __expf(-edc * (float)(t + 1));
                        s.gf[rloc][t] = pk(gate, (1.0f - gate) * gd);
                    }
                }
            }

            float curA = lastA, curB = lastB;
            float* outrowA = out + (size_t)rowA * TT;
            float* outrowB = out + (size_t)rowB * TT;

#pragma unroll 1
            for (int t = 0; t <= TT; t++) {
                u64 a1 = __shfl_xor_sync(FULL, hqA, 1);
                u64 b1 = __shfl_xor_sync(FULL, hqB, 1);
                u64 a2 = __shfl_xor_sync(FULL, hqA, 2);
                u64 b2 = __shfl_xor_sync(FULL, hqB, 2);
                u64 a3 = __shfl_xor_sync(FULL, hqA, 3);
                u64 b3 = __shfl_xor_sync(FULL, hqB, 3);

                u64 ppA = ffma2(hqA, wo4[0], 0ULL);
                u64 ppB = ffma2(hqB, wo4[0], 0ULL);
                ppA = ffma2(a1, wo4[1], ppA);   ppB = ffma2(b1, wo4[1], ppB);
                ppA = ffma2(a2, wo4[2], ppA);   ppB = ffma2(b2, wo4[2], ppB);
                ppA = ffma2(a3, wo4[3], ppA);   ppB = ffma2(b3, wo4[3], ppB);
                float2 pfA = upk(ppA), pfB = upk(ppB);
                float pA = pfA.x + pfA.y + bo_r;
                float pB = pfB.x + pfB.y + bo_r;
                if (t > 0) {
                    curA = pA; curB = pB;
                    if (((t - 1) & 3) == sub) {
                        float2 ggA = upk(s.gf[rl][t - 1]);
                        float2 ggB = upk(s.gf[rl + 32][t - 1]);
                        outrowA[t - 1] = fmaf(ggA.x, pA, ggA.y);
                        outrowB[t - 1] = fmaf(ggB.x, pB, ggB.y);
                    }
                }
                if (t == TT) break;

                float2 fa0 = upk(hqA), fa1 = upk(a1), fa2 = upk(a2), fa3 = upk(a3);
                float2 fb0 = upk(hqB), fb1 = upk(b1), fb2 = upk(b2), fb3 = upk(b3);
                u64 curdA = dup2(curA), curdB = dup2(curB);
                u64 arA = ffma2(wihr, curdA, bsr),  arB = ffma2(wihr, curdB, bsr);
                u64 azA = ffma2(wihz, curdA, bsz),  azB = ffma2(wihz, curdB, bsz);
                u64 aiA = ffma2(wihn, curdA, bain), aiB = ffma2(wihn, curdB, bain);
                u64 ahA = bahn, ahB = bahn;
#define STEPJ(idx, hvA, hvB) { u64 hdA = dup2(hvA), hdB = dup2(hvB); \
                arA = ffma2(whr[idx], hdA, arA);  arB = ffma2(whr[idx], hdB, arB); \
                azA = ffma2(whz[idx], hdA, azA);  azB = ffma2(whz[idx], hdB, azB); \
                ahA = ffma2(whn[idx], hdA, ahA);  ahB = ffma2(whn[idx], hdB, ahB); }
                STEPJ(0, fa0.x, fb0.x) STEPJ(1, fa0.y, fb0.y)
                STEPJ(2, fa1.x, fb1.x) STEPJ(3, fa1.y, fb1.y)
                STEPJ(4, fa2.x, fb2.x) STEPJ(5, fa2.y, fb2.y)
                STEPJ(6, fa3.x, fb3.x) STEPJ(7, fa3.y, fb3.y)
#undef STEPJ
                u64 rA = sigmoid2h(arA), rB = sigmoid2h(arB);
                u64 zA = sigmoid2h(azA), zB = sigmoid2h(azB);
                u64 nA = tanh2t(ffma2(rA, ahA, aiA));
                u64 nB = tanh2t(ffma2(rB, ahB, aiB));
                u64 dA = ffma2(nA, NEG1U, hqA);
                u64 dB = ffma2(nB, NEG1U, hqB);
                hqA = ffma2(zA, dA, nA);
                hqB = ffma2(zB, dB, nB);
            }
        }
        // next tile's proj begins with cp_wait + __syncthreads, which also
        // protects res/gf/xs from overwrite while any warp lags in GRU.
    }
}

extern "C" void kernel_launch(void* const* d_in, const int* in_sizes, int n_in,
                              void* d_out, int out_size) {
    const float* x         = (const float*)d_in[0];
    const float* last_step = (const float*)d_in[1];
    const float* W_ih      = (const float*)d_in[2];
    const float* W_hh      = (const float*)d_in[3];
    const float* b_ih      = (const float*)d_in[4];
    const float* b_hh      = (const float*)d_in[5];
    const float* Wp        = (const float*)d_in[6];
    const float* bp        = (const float*)d_in[7];
    const float* Wo        = (const float*)d_in[8];
    const float* bo        = (const float*)d_in[9];
    const float* Wg1       = (const float*)d_in[10];
    const float* bg1       = (const float*)d_in[11];
    const float* Wg2       = (const float*)d_in[12];
    const float* bg2       = (const float*)d_in[13];
    const float* log_decay = (const float*)d_in[14];
    float* out = (float*)d_out;

    cudaFuncSetAttribute(fused_kernel, cudaFuncAttributeMaxDynamicSharedMemorySize,
                         (int)sizeof(Smem));
    fused_kernel<<<GRIDX, BLK, sizeof(Smem)>>>(x, last_step, W_ih, W_hh, b_ih, b_hh,
                                               Wp, bp, Wo, bo, Wg1, bg1, Wg2, bg2,
                                               log_decay, out);
}

// round 17
// speedup vs baseline: 1.2074x; 1.2074x over previous
#include <cuda_runtime.h>

#define BB 32
#define NN 4096
#define DD 256
#define HH 8
#define TT 28
#define ROWS (BB * NN)
#define BLKA 128
#define RPBA 32             // rows per tile, kernel A
#define NTILES (ROWS / RPBA)
#define GRIDA (148 * 3)     // persistent: 3 CTAs per SM
#define BLKB 128
#define RPBB 64             // rows per block, kernel B (4 threads/row, 2 rows/thread)

typedef unsigned long long u64;

// 8 MB scratch: per row 16 floats = [h0 lanes 0..7 | g1pre lanes 0..7]
__device__ __align__(16) float g_proj[ROWS * 16];

// ---------- packed f32x2 ops on opaque u64 register pairs ----------
__device__ __forceinline__ u64 ffma2(u64 a, u64 b, u64 c) {
    u64 d; asm("fma.rn.f32x2 %0, %1, %2, %3;" : "=l"(d) : "l"(a), "l"(b), "l"(c)); return d;
}
__device__ __forceinline__ u64 fadd2(u64 a, u64 b) {
    u64 d; asm("add.rn.f32x2 %0, %1, %2;" : "=l"(d) : "l"(a), "l"(b)); return d;
}
__device__ __forceinline__ u64 pk(float lo, float hi) {
    u64 r; asm("mov.b64 %0, {%1,%2};" : "=l"(r) : "f"(lo), "f"(hi)); return r;
}
__device__ __forceinline__ float2 upk(u64 v) {
    float2 f; asm("mov.b64 {%0,%1}, %2;" : "=f"(f.x), "=f"(f.y) : "l"(v)); return f;
}
__device__ __forceinline__ u64 dup2(float v) { return pk(v, v); }

__device__ __forceinline__ float tanhapx(float x) {
    float y; asm("tanh.approx.f32 %0, %1;" : "=f"(y) : "f"(x)); return y;
}

__device__ __forceinline__ void cp16(void* smem_dst, const void* gsrc) {
    unsigned sa = (unsigned)__cvta_generic_to_shared(smem_dst);
    asm volatile("cp.async.cg.shared.global [%0], [%1], 16;" :: "r"(sa), "l"(gsrc) : "memory");
}
__device__ __forceinline__ void cp_commit() {
    asm volatile("cp.async.commit_group;" ::: "memory");
}
__device__ __forceinline__ void cp_wait0() {
    asm volatile("cp.async.wait_group 0;" ::: "memory");
}
__device__ __forceinline__ void cp_wait1() {
    asm volatile("cp.async.wait_group 1;" ::: "memory");
}

#define NEG1U 0xBF800000BF800000ULL  // (-1.0f, -1.0f)

// input pre-scaled by 0.5: sigmoid(2v) = 0.5*tanh(v) + 0.5
__device__ __forceinline__ u64 sigmoid2h(u64 v) {
    float2 f = upk(v);
    return pk(fmaf(0.5f, tanhapx(f.x), 0.5f), fmaf(0.5f, tanhapx(f.y), 0.5f));
}
__device__ __forceinline__ u64 tanh2t(u64 v) {
    float2 f = upk(v);
    return pk(tanhapx(f.x), tanhapx(f.y));
}

// ============ Kernel A: persistent projection GEMM with cp.async pipeline ============
struct SmemA {
    float4     xs[2][RPBA][32];   // double-buffered stage (32KB)
    ulonglong2 wq[64 * 17];       // [chunk][e*4 + pg*2 + i] + pad (17KB)
};

__global__ void __launch_bounds__(BLKA)
proj_kernel(const float* __restrict__ x,
            const float* __restrict__ Wp, const float* __restrict__ Wg1) {
    __shared__ SmemA s;
    const int tid = threadIdx.x;
    const unsigned FULL = 0xFFFFFFFFu;

    const int pg  = tid >> 6;
    const int rgp = (tid >> 4) & 3;
    const int ds  = tid & 15;

    for (int idx = tid; idx < 64 * 16; idx += BLKA) {
        int chunk = idx >> 4, r = idx & 15;
        int e = r >> 2, pgw = (r >> 1) & 1, i = r & 1;
        int d = chunk * 4 + e;
        const float* W = pgw ? Wg1 : Wp;
        s.wq[chunk * 17 + e * 4 + pgw * 2 + i] = make_ulonglong2(
            pk(W[(4 * i + 0) * DD + d], W[(4 * i + 1) * DD + d]),
            pk(W[(4 * i + 2) * DD + d], W[(4 * i + 3) * DD + d]));
    }

    auto issue_unit = [&](int tile, int cst, int buf) {
#pragma unroll
        for (int k = 0; k < 8; k++) {
            int f = k * BLKA + tid;
            int row = f >> 5, q = f & 31;
            cp16(&s.xs[buf][row][q],
                 x + (size_t)(tile * RPBA + row) * DD + cst * 128 + q * 4);
        }
        cp_commit();
    };

    const int stride = gridDim.x;
    const int t0 = blockIdx.x;
    if (t0 >= NTILES) return;

    u64 acc[32];
    issue_unit(t0, 0, 0);

    int k = 0;
    for (int tile = t0; tile < NTILES; tile += stride) {
#pragma unroll 1
        for (int cst = 0; cst < 2; cst++, k++) {
            int buf = k & 1;
            cp_wait0();
            __syncthreads();
            {
                int nk = k + 1;
                int ncst = nk & 1;
                int ntile = tile + (ncst == 0 ? stride : 0);
                if (ntile < NTILES) issue_unit(ntile, ncst, buf ^ 1);
            }
            if (cst == 0) {
#pragma unroll
                for (int i = 0; i < 32; i++) acc[i] = 0ULL;
            }
#pragma unroll 1
            for (int m2 = 0; m2 < 2; m2++) {
                int chunkL = ds + 16 * m2;
                int chunkG = cst * 32 + chunkL;
                ulonglong2 w[8];
#pragma unroll
                for (int e = 0; e < 4; e++) {
                    w[2 * e]     = s.wq[chunkG * 17 + e * 4 + pg * 2 + 0];
                    w[2 * e + 1] = s.wq[chunkG * 17 + e * 4 + pg * 2 + 1];
                }
#pragma unroll
                for (int r = 0; r < 8; r++) {
                    float4 xv = s.xs[buf][rgp * 8 + r][chunkL];
#pragma unroll
                    for (int e = 0; e < 4; e++) {
                        float xe = (e == 0) ? xv.x : (e == 1) ? xv.y : (e == 2) ? xv.z : xv.w;
                        u64 xd = dup2(xe);
                        acc[r * 4 + 0] = ffma2(w[2 * e].x,     xd, acc[r * 4 + 0]);
                        acc[r * 4 + 1] = ffma2(w[2 * e].y,     xd, acc[r * 4 + 1]);
                        acc[r * 4 + 2] = ffma2(w[2 * e + 1].x, xd, acc[r * 4 + 2]);
                        acc[r * 4 + 3] = ffma2(w[2 * e + 1].y, xd, acc[r * 4 + 3]);
                    }
                }
            }
            if (cst == 1) {
#define REDROUND(cnt, bit) { int db = ds & (bit); \
    _Pragma("unroll") \
    for (int i = 0; i < (cnt) / 2; i++) { \
        u64 snd = db ? acc[i] : acc[i + (cnt) / 2]; \
        u64 rcv = __shfl_xor_sync(FULL, snd, (bit)); \
        u64 kp  = db ? acc[i + (cnt) / 2] : acc[i]; \
        acc[i] = fadd2(kp, rcv); \
    } }
                REDROUND(32, 1)
                REDROUND(16, 2)
                REDROUND(8, 4)
                REDROUND(4, 8)
#undef REDROUND
                int r_own = 4 * (ds & 1) + 2 * ((ds >> 1) & 1) + ((ds >> 2) & 1);
                int b = (ds >> 3) & 1;
                int row = tile * RPBA + rgp * 8 + r_own;
                *(ulonglong2*)&g_proj[row * 16 + pg * 8 + 4 * b] =
                    make_ulonglong2(acc[0], acc[1]);
            }
        }
    }
}

// ====== Kernel B: GRU rollout (4 threads/row, 2 rows/thread, weights in regs) =======
struct SmemB {
    u64 gf[RPBB][TT];            // (gate, (1-gate)*decay) per row per t (14KB)
};

__global__ void __launch_bounds__(BLKB)
gru_kernel(const float* __restrict__ last_step,
           const float* __restrict__ W_ih, const float* __restrict__ W_hh,
           const float* __restrict__ b_ih, const float* __restrict__ b_hh,
           const float* __restrict__ bp, const float* __restrict__ Wo,
           const float* __restrict__ bo, const float* __restrict__ bg1,
           const float* __restrict__ Wg2, const float* __restrict__ bg2,
           const float* __restrict__ log_decay, float* __restrict__ out) {
    __shared__ SmemB s;
    const int tid = threadIdx.x;
    const int sub = tid & 3;
    const int rl  = tid >> 2;           // local row 0..31 (row A); row B = rl + 32
    const int rb  = blockIdx.x * RPBB;
    const int rowA = rb + rl, rowB = rowA + 32;
    const int L0  = 2 * sub, L1 = L0 + 1;
    const unsigned FULL = 0xFFFFFFFFu;

    const u64 bpq  = pk(bp[L0], bp[L1]);
    const u64 bg1q = pk(bg1[L0], bg1[L1]);
    u64 hqA, g1qA, hqB, g1qB;
    {
        float2 hv = *(const float2*)&g_proj[rowA * 16 + 2 * sub];
        float2 gv = *(const float2*)&g_proj[rowA * 16 + 8 + 2 * sub];
        hqA = fadd2(pk(hv.x, hv.y), bpq);
        float2 f = upk(fadd2(pk(gv.x, gv.y), bg1q));
        g1qA = pk(fmaxf(f.x, 0.0f), fmaxf(f.y, 0.0f));
    }
    {
        float2 hv = *(const float2*)&g_proj[rowB * 16 + 2 * sub];
        float2 gv = *(const float2*)&g_proj[rowB * 16 + 8 + 2 * sub];
        hqB = fadd2(pk(hv.x, hv.y), bpq);
        float2 f = upk(fadd2(pk(gv.x, gv.y), bg1q));
        g1qB = pk(fmaxf(f.x, 0.0f), fmaxf(f.y, 0.0f));
    }

    const float lastA = last_step[rowA];
    const float lastB = last_step[rowB];

    {
        float edc = __expf(log_decay[0]);
        int j0 = 2 * (sub ^ 0), j1 = 2 * (sub ^ 1), j2 = 2 * (sub ^ 2), j3 = 2 * (sub ^ 3);
#pragma unroll
        for (int which = 0; which < 2; which++) {
            u64 gq = which ? g1qB : g1qA;
            float lastv = which ? lastB : lastA;
            int rloc = rl + 32 * which;
            u64 gA = __shfl_xor_sync(FULL, gq, 1);
            u64 gB = __shfl_xor_sync(FULL, gq, 2);
            u64 gC = __shfl_xor_sync(FULL, gq, 3);
            float2 g0 = upk(gq), g1v = upk(gA), g2v = upk(gB), g3v = upk(gC);
#pragma unroll
            for (int kk = 0; kk < 7; kk++) {
                int t = 4 * kk + sub;
                const float* wr = Wg2 + t * HH;
                float lg = bg2[t];
                lg = fmaf(g0.x, wr[j0], lg);     lg = fmaf(g0.y, wr[j0 + 1], lg);
                lg = fmaf(g1v.x, wr[j1], lg);    lg = fmaf(g1v.y, wr[j1 + 1], lg);
                lg = fmaf(g2v.x, wr[j2], lg);    lg = fmaf(g2v.y, wr[j2 + 1], lg);
                lg = fmaf(g3v.x, wr[j3], lg);    lg = fmaf(g3v.y, wr[j3 + 1], lg);
                float gate = fmaf(0.5f, tanhapx(0.5f * lg), 0.5f);
                float gd = lastv * __expf(-edc * (float)(t + 1));
                s.gf[rloc][t] = pk(gate, (1.0f - gate) * gd);
            }
        }
    }

    // hoist GRU weights (slot-permuted to match shuffles); r/z pre-scaled by 0.5
    u64 whr[8], whz[8], whn[8];
#pragma unroll
    for (int p = 0; p < 4; p++) {
        int j0 = 2 * (sub ^ p);
#pragma unroll
        for (int b = 0; b < 2; b++) {
            int j = j0 + b, idx = 2 * p + b;
            whr[idx] = pk(0.5f * W_hh[L0 * HH + j],        0.5f * W_hh[L1 * HH + j]);
            whz[idx] = pk(0.5f * W_hh[(8 + L0) * HH + j],  0.5f * W_hh[(8 + L1) * HH + j]);
            whn[idx] = pk(W_hh[(16 + L0) * HH + j],        W_hh[(16 + L1) * HH + j]);
        }
    }
    const u64 wo_own = pk(Wo[L0], Wo[L1]);   // own-lane Wo pair (butterfly pred)
    u64 wihr = pk(0.5f * W_ih[L0], 0.5f * W_ih[L1]);
    u64 wihz = pk(0.5f * W_ih[8 + L0], 0.5f * W_ih[8 + L1]);
    u64 wihn = pk(W_ih[16 + L0], W_ih[16 + L1]);
    u64 bsr  = pk(0.5f * (b_ih[L0] + b_hh[L0]), 0.5f * (b_ih[L1] + b_hh[L1]));
    u64 bsz  = pk(0.5f * (b_ih[8 + L0] + b_hh[8 + L0]), 0.5f * (b_ih[8 + L1] + b_hh[8 + L1]));
    u64 bain = pk(b_ih[16 + L0], b_ih[16 + L1]);
    u64 bahn = pk(b_hh[16 + L0], b_hh[16 + L1]);
    const float bo_r = bo[0];

    float curA = lastA, curB = lastB;
    float* outrowA = out + (size_t)rowA * TT;
    float* outrowB = out + (size_t)rowB * TT;

#pragma unroll 1
    for (int t = 0; t <= TT; t++) {
        // pred(t-1) via own-lane partial + quad butterfly (both rows packed in one u64).
        // xor-butterfly produces bitwise-identical sums in all 4 lanes -> quad stays
        // in lockstep on `cur`.
        u64 ppA = ffma2(hqA, wo_own, 0ULL);
        u64 ppB = ffma2(hqB, wo_own, 0ULL);
        float2 qa = upk(ppA), qb = upk(ppB);
        u64 pp = pk(qa.x + qa.y, qb.x + qb.y);
        pp = fadd2(pp, __shfl_xor_sync(FULL, pp, 1));
        pp = fadd2(pp, __shfl_xor_sync(FULL, pp, 2));
        float2 pf = upk(pp);
        float pA = pf.x + bo_r;
        float pB = pf.y + bo_r;

        // h-exchange butterflies (for gh)
        u64 a1 = __shfl_xor_sync(FULL, hqA, 1);
        u64 b1 = __shfl_xor_sync(FULL, hqB, 1);
        u64 a2 = __shfl_xor_sync(FULL, hqA, 2);
        u64 b2 = __shfl_xor_sync(FULL, hqB, 2);
        u64 a3 = __shfl_xor_sync(FULL, hqA, 3);
        u64 b3 = __shfl_xor_sync(FULL, hqB, 3);

        if (t > 0) {
            curA = pA; curB = pB;
            if (((t - 1) & 3) == sub) {
                float2 ggA = upk(s.gf[rl][t - 1]);
                float2 ggB = upk(s.gf[rl + 32][t - 1]);
                outrowA[t - 1] = fmaf(ggA.x, pA, ggA.y);
                outrowB[t - 1] = fmaf(ggB.x, pB, ggB.y);
            }
        }
        if (t == TT) break;

        float2 fa0 = upk(hqA), fa1 = upk(a1), fa2 = upk(a2), fa3 = upk(a3);
        float2 fb0 = upk(hqB), fb1 = upk(b1), fb2 = upk(b2), fb3 = upk(b3);
        u64 curdA = dup2(curA), curdB = dup2(curB);
        u64 arA = ffma2(wihr, curdA, bsr), arB = ffma2(wihr, curdB, bsr);
        u64 azA = ffma2(wihz, curdA, bsz), azB = ffma2(wihz, curdB, bsz);
        u64 aiA = ffma2(wihn, curdA, bain), aiB = ffma2(wihn, curdB, bain);
        u64 ahA = bahn, ahB = bahn;
#define STEPJ(idx, hvA, hvB) { u64 hdA = dup2(hvA), hdB = dup2(hvB); \
        arA = ffma2(whr[idx], hdA, arA);  arB = ffma2(whr[idx], hdB, arB); \
        azA = ffma2(whz[idx], hdA, azA);  azB = ffma2(whz[idx], hdB, azB); \
        ahA = ffma2(whn[idx], hdA, ahA);  ahB = ffma2(whn[idx], hdB, ahB); }
        STEPJ(0, fa0.x, fb0.x) STEPJ(1, fa0.y, fb0.y)
        STEPJ(2, fa1.x, fb1.x) STEPJ(3, fa1.y, fb1.y)
        STEPJ(4, fa2.x, fb2.x) STEPJ(5, fa2.y, fb2.y)
        STEPJ(6, fa3.x, fb3.x) STEPJ(7, fa3.y, fb3.y)
#undef STEPJ
        u64 rA = sigmoid2h(arA), rB = sigmoid2h(arB);
        u64 zA = sigmoid2h(azA), zB = sigmoid2h(azB);
        u64 nA = tanh2t(ffma2(rA, ahA, aiA));
        u64 nB = tanh2t(ffma2(rB, ahB, aiB));
        u64 dA = ffma2(nA, NEG1U, hqA);
        u64 dB = ffma2(nB, NEG1U, hqB);
        hqA = ffma2(zA, dA, nA);
        hqB = ffma2(zB, dB, nB);
    }
}

extern "C" void kernel_launch(void* const* d_in, const int* in_sizes, int n_in,
                              void* d_out, int out_size) {
    const float* x         = (const float*)d_in[0];
    const float* last_step = (const float*)d_in[1];
    const float* W_ih      = (const float*)d_in[2];
    const float* W_hh      = (const float*)d_in[3];
    const float* b_ih      = (const float*)d_in[4];
    const float* b_hh      = (const float*)d_in[5];
    const float* Wp        = (const float*)d_in[6];
    const float* bp        = (const float*)d_in[7];
    const float* Wo        = (const float*)d_in[8];
    const float* bo        = (const float*)d_in[9];
    const float* Wg1       = (const float*)d_in[10];
    const float* bg1       = (const float*)d_in[11];
    const float* Wg2       = (const float*)d_in[12];
    const float* bg2       = (const float*)d_in[13];
    const float* log_decay = (const float*)d_in[14];
    float* out = (float*)d_out;

    proj_kernel<<<GRIDA, BLKA>>>(x, Wp, Wg1);
    gru_kernel<<<ROWS / RPBB, BLKB>>>(last_step, W_ih, W_hh, b_ih, b_hh,
                                      bp, Wo, bo, bg1, Wg2, bg2, log_decay, out);
}